// round 6
// baseline (speedup 1.0000x reference)
#include <cuda_runtime.h>
#include <cstdint>

#define MAXB   64
#define MAXN   16
#define NC     21
#define MTPB   256
#define MPPT   4
#define MROWS  (MTPB*MPPT)      // 1024
#define NABLK  24
#define MAXPP  24576
#define LTILE  128
#define LROWS  1024

// -------- scratch (__device__ globals; overwritten every launch) ----------
__device__ int                g_matchv[MAXB * MAXPP];   // bestn | pos<<31
__device__ float              g_mine  [MAXB * MAXPP];   // lse - row[0] (>= 0)
__device__ unsigned long long g_cK[MAXB * NABLK * MAXN];
__device__ float              g_bl[MAXB];
__device__ float              g_bc[MAXB];
__device__ int                g_bn[MAXB];
__device__ int                g_ctr = 0;                // reset by last block

__device__ __forceinline__ float smooth_l1(float d) {
    float ad = fabsf(d);
    return (ad < 1.0f) ? 0.5f * d * d : ad - 0.5f;
}

__device__ __forceinline__ void cp16(float* dst, const float4* src) {
    unsigned s = (unsigned)__cvta_generic_to_shared(dst);
    asm volatile("cp.async.cg.shared.global [%0], [%1], 16;\n" :: "r"(s), "l"(src));
}

// ==========================================================================
// Fused: blockIdx.x < nA -> IoU matching (ALU); else -> lse stream (DRAM).
__global__ __launch_bounds__(256, 6) void k_fused(
    const float* __restrict__ conf,
    const float* __restrict__ priors,
    const float* __restrict__ truths,
    int P, int N, int nA)
{
    __shared__ __align__(16) float s_conf[2 * LTILE * NC];   // 21.5 KB
    __shared__ float4 s_t[MAXN];
    __shared__ float  s_area[MAXN];
    __shared__ unsigned long long s_best[MAXN];

    int b   = blockIdx.y;
    int tid = threadIdx.x;

    if (blockIdx.x < nA) {
        // ================= MATCH PATH =================
        int p0   = blockIdx.x * MROWS;
        int lane = tid & 31;

        if (tid < MAXN) {
            s_best[tid] = 0ULL;
            if (tid < N) {
                float4 t = reinterpret_cast<const float4*>(truths)[b * N + tid];
                s_t[tid] = t;
                s_area[tid] = (t.z - t.x) * (t.w - t.y);
            }
        }
        __syncthreads();

        float px1[MPPT], py1[MPPT], px2[MPPT], py2[MPPT], ab[MPPT];
        #pragma unroll
        for (int i = 0; i < MPPT; ++i) {
            int p  = p0 + i * MTPB + tid;
            int pc = min(p, P - 1);                 // clamp; dups lose ties via ~p
            float4 pr = reinterpret_cast<const float4*>(priors)[pc];
            float hx = pr.z * 0.5f, hy = pr.w * 0.5f;
            px1[i] = pr.x - hx; py1[i] = pr.y - hy;
            px2[i] = pr.x + hx; py2[i] = pr.y + hy;
            ab[i]  = pr.z * pr.w;
        }

        float bt[MPPT];
        int   bn[MPPT];
        #pragma unroll
        for (int i = 0; i < MPPT; ++i) { bt[i] = -1.f; bn[i] = 0; }

        #pragma unroll
        for (int n = 0; n < MAXN; ++n) {
            if (n < N) {
                float4 t = s_t[n];
                float sa = s_area[n];
                float biou = -1.f;
                int   bp   = 0x7FFFFFFF;
                #pragma unroll
                for (int i = 0; i < MPPT; ++i) {
                    float w = fmaxf(fminf(t.z, px2[i]) - fmaxf(t.x, px1[i]), 0.f);
                    float h = fmaxf(fminf(t.w, py2[i]) - fmaxf(t.y, py1[i]), 0.f);
                    float inter = w * h;
                    float uni   = sa + ab[i] - inter;
                    float iou   = __fdividef(inter, uni);
                    if (iou > bt[i]) { bt[i] = iou; bn[i] = n; }               // tie -> lowest n
                    if (iou > biou)  { biou = iou; bp = p0 + i * MTPB + tid; } // tie -> lowest p
                }
                unsigned long long key =
                    ((unsigned long long)__float_as_uint(fmaxf(biou, 0.f)) << 32)
                    | (unsigned)~bp;
                #pragma unroll
                for (int o = 16; o; o >>= 1) {
                    unsigned long long ok = __shfl_down_sync(0xFFFFFFFFu, key, o);
                    key = (ok > key) ? ok : key;
                }
                if (lane == 0) atomicMax(&s_best[n], key);
            }
        }

        #pragma unroll
        for (int i = 0; i < MPPT; ++i) {
            int p = p0 + i * MTPB + tid;
            if (p < P) {
                int pos = (bt[i] >= 0.5f) ? 1 : 0;
                g_matchv[(size_t)b * P + p] = bn[i] | (pos << 31);
            }
        }
        __syncthreads();
        if (tid < MAXN)
            g_cK[((size_t)b * NABLK + blockIdx.x) * MAXN + tid] = s_best[tid];

    } else {
        // ================= LSE PATH =================
        int bx   = blockIdx.x - nA;
        int r0   = bx * LROWS;
        int rows = min(LROWS, P - r0);
        int nt   = (rows + LTILE - 1) / LTILE;

        auto stage = [&](int t) {
            int tr = min(LTILE, rows - t * LTILE);
            int total = tr * NC;
            int n4 = total >> 2;
            const float* srcf = conf + ((size_t)b * P + r0 + t * LTILE) * NC;
            const float4* src4 = reinterpret_cast<const float4*>(srcf);
            float* dst = s_conf + (t & 1) * (LTILE * NC);
            for (int i = tid; i < n4; i += MTPB) cp16(dst + i * 4, src4 + i);
            for (int i = (n4 << 2) + tid; i < total; i += MTPB) dst[i] = srcf[i];
            asm volatile("cp.async.commit_group;\n");
        };

        stage(0);
        for (int t = 0; t < nt; ++t) {
            if (t + 1 < nt) {
                stage(t + 1);
                asm volatile("cp.async.wait_group 1;\n");
            } else {
                asm volatile("cp.async.wait_group 0;\n");
            }
            __syncthreads();

            int r = t * LTILE + tid;
            if (tid < LTILE && r < rows) {
                const float* row = s_conf + (t & 1) * (LTILE * NC) + tid * NC;
                float e0 = 0.f, e1 = 0.f, e2 = 0.f, e3 = 0.f;
                #pragma unroll
                for (int c = 0; c < NC; c += 4) {
                    e0 += __expf(row[c]);
                    if (c + 1 < NC) e1 += __expf(row[c + 1]);
                    if (c + 2 < NC) e2 += __expf(row[c + 2]);
                    if (c + 3 < NC) e3 += __expf(row[c + 3]);
                }
                float lse = __logf((e0 + e1) + (e2 + e3));
                g_mine[(size_t)b * P + r0 + r] = lse - row[0];   // >= 0
            }
            __syncthreads();
        }
    }
}

// ==========================================================================
// suffix-scan over 4096-bin histogram; 1024 threads, 4 bins each.
__device__ __forceinline__ void find_threshold(
    int* s_hist, int k, int tid, int* s_wt, int* s_out)
{
    int w = tid >> 5, lane = tid & 31;
    int base = tid * 4;
    int l[4]; int loc = 0;
    #pragma unroll
    for (int j = 0; j < 4; ++j) { l[j] = s_hist[base + j]; loc += l[j]; }
    int incl = loc;
    #pragma unroll
    for (int o = 1; o < 32; o <<= 1) {
        int x = __shfl_up_sync(0xFFFFFFFFu, incl, o);
        if (lane >= o) incl += x;
    }
    int wsum = __shfl_sync(0xFFFFFFFFu, incl, 31);
    if (lane == 31) s_wt[w] = wsum;
    __syncthreads();
    int wa = 0;
    #pragma unroll
    for (int w2 = 0; w2 < 32; ++w2) if (w2 > w) wa += s_wt[w2];
    int above = wa + (wsum - incl);          // count in bins >= base+4
    if (above < k && above + loc >= k) {
        int run = 0;
        #pragma unroll
        for (int j = 3; j >= 0; --j) {
            run += l[j];
            if (above + run >= k) { s_out[0] = base + j; s_out[1] = above + run - l[j]; break; }
        }
    }
    __syncthreads();
}

// ==========================================================================
// k_select: per batch — positive scan (CE/loc/pos, register-zero the mined
// value), forced-prior corrections, then two-level 12+12-bit histogram
// top-k sum. Last block reduces all batches into the output.
__global__ __launch_bounds__(1024) void k_select(
    const float* __restrict__ loc,
    const float* __restrict__ conf,
    const float* __restrict__ priors,
    const float* __restrict__ truths,
    const int*   __restrict__ labels,
    int P, int N, int nA, float* __restrict__ out)
{
    int b = blockIdx.x, tid = threadIdx.x;
    int w = tid >> 5, lane = tid & 31;

    __shared__ int    s_hist[4096];
    __shared__ int    s_wt[32];
    __shared__ int    s_out[2];
    __shared__ float  s_fs[32];
    __shared__ int    s_cs[32];
    __shared__ float4 s_t[MAXN];
    __shared__ int    s_lab[MAXN], s_fp[MAXN];
    __shared__ float  s_L, s_Cp, s_corrL, s_corrC;
    __shared__ int    s_np, s_corrN, s_last;

    if (tid < N) {
        s_t[tid]   = reinterpret_cast<const float4*>(truths)[b * N + tid];
        s_lab[tid] = labels[b * N + tid];
    }
    #pragma unroll
    for (int i = 0; i < 4; ++i) s_hist[tid + i * 1024] = 0;
    __syncthreads();

    // ---- scan: load mine + match, handle positives inline ----
    const int V4 = 6;            // 6 * 1024 * 4 = 24576 >= P
    float4 v4[V4];
    float L = 0.f, C = 0.f; int n = 0;
    const float4* mv  = reinterpret_cast<const float4*>(g_mine   + (size_t)b * P);
    const int4*   mm4 = reinterpret_cast<const int4*>  (g_matchv + (size_t)b * P);
    int n4 = P >> 2;

    auto do_pos = [&](int mm, float& vref, int p) {
        if (mm < 0) {
            int bnn = mm & 0x7FFFFFFF;
            const float* crow = conf + ((size_t)b * P + p) * NC;
            float lse = vref + crow[0];
            C += lse - crow[s_lab[bnn] + 1];
            n++;
            float4 tt = s_t[bnn];
            float4 pr = reinterpret_cast<const float4*>(priors)[p];
            float gx = __fdividef((tt.x + tt.z) * 0.5f - pr.x, 0.1f * pr.z);
            float gy = __fdividef((tt.y + tt.w) * 0.5f - pr.y, 0.1f * pr.w);
            float gw = __logf(__fdividef(tt.z - tt.x, pr.z)) * 5.0f;
            float gh = __logf(__fdividef(tt.w - tt.y, pr.w)) * 5.0f;
            float4 ld = reinterpret_cast<const float4*>(loc)[(size_t)b * P + p];
            L += smooth_l1(ld.x - gx) + smooth_l1(ld.y - gy)
               + smooth_l1(ld.z - gw) + smooth_l1(ld.w - gh);
            vref = 0.f;
        }
    };

    #pragma unroll
    for (int i = 0; i < V4; ++i) {
        int j = tid + i * 1024;
        float4 v = make_float4(0.f, 0.f, 0.f, 0.f);
        if (j < n4) {
            v = mv[j];
            int4 m = mm4[j];
            int p = 4 * j;
            do_pos(m.x, v.x, p);
            do_pos(m.y, v.y, p + 1);
            do_pos(m.z, v.z, p + 2);
            do_pos(m.w, v.w, p + 3);
        }
        v4[i] = v;
    }
    int tail = P & 3;
    float vex = 0.f;
    if (tid < tail) {
        int p = (P & ~3) + tid;
        vex = g_mine[(size_t)b * P + p];
        do_pos(g_matchv[(size_t)b * P + p], vex, p);
    }

    // reduce scan partials
    #pragma unroll
    for (int o = 16; o; o >>= 1) {
        L += __shfl_down_sync(0xFFFFFFFFu, L, o);
        C += __shfl_down_sync(0xFFFFFFFFu, C, o);
        n += __shfl_down_sync(0xFFFFFFFFu, n, o);
    }
    if (lane == 0) { s_fs[w] = L; s_cs[w] = n; }
    __syncthreads();
    {
        __shared__ float s_fc[32];
        if (lane == 0) s_fc[w] = C;
        __syncthreads();
        if (tid == 0) {
            float Lt = 0.f, Ct = 0.f; int nt = 0;
            #pragma unroll
            for (int i = 0; i < 32; ++i) { Lt += s_fs[i]; Ct += s_fc[i]; nt += s_cs[i]; }
            s_L = Lt; s_Cp = Ct; s_np = nt;
        }
    }
    __syncthreads();

    // ---- warp 0: forced best prior per truth + dedupe + corrections ----
    if (w == 0) {
        unsigned long long best = 0ULL;
        if (lane < N)
            for (int j = 0; j < nA; ++j) {
                unsigned long long k2 = g_cK[((size_t)b * NABLK + j) * MAXN + lane];
                best = (k2 > best) ? k2 : best;
            }
        int fp = (lane < N) ? (int)~(unsigned)best : -1;
        bool valid = (lane < N);
        #pragma unroll
        for (int m = 0; m < MAXN; ++m) {
            int pm = __shfl_sync(0xFFFFFFFFu, fp, m);
            if (m < N && m > lane && pm == fp) valid = false;
        }
        float dL = 0.f, dC = 0.f; int dN = 0;
        if (valid) {
            int p = fp;
            int mm = g_matchv[(size_t)b * P + p];
            const float* crow = conf + ((size_t)b * P + p) * NC;
            float lse = g_mine[(size_t)b * P + p] + crow[0];
            float4 pr = reinterpret_cast<const float4*>(priors)[p];
            float4 ld = reinterpret_cast<const float4*>(loc)[(size_t)b * P + p];
            float izx = __fdividef(1.f, 0.1f * pr.z);
            float izy = __fdividef(1.f, 0.1f * pr.w);
            {   // add forced contribution (truth = lane)
                float4 tt = s_t[lane];
                dC += lse - crow[s_lab[lane] + 1];
                float gx = ((tt.x + tt.z) * 0.5f - pr.x) * izx;
                float gy = ((tt.y + tt.w) * 0.5f - pr.y) * izy;
                float gw = __logf(__fdividef(tt.z - tt.x, pr.z)) * 5.0f;
                float gh = __logf(__fdividef(tt.w - tt.y, pr.w)) * 5.0f;
                dL += smooth_l1(ld.x - gx) + smooth_l1(ld.y - gy)
                    + smooth_l1(ld.z - gw) + smooth_l1(ld.w - gh);
                dN += 1;
            }
            if (mm < 0) {   // subtract scan's version
                int bnn = mm & 0x7FFFFFFF;
                float4 tt = s_t[bnn];
                dC -= lse - crow[s_lab[bnn] + 1];
                float gx = ((tt.x + tt.z) * 0.5f - pr.x) * izx;
                float gy = ((tt.y + tt.w) * 0.5f - pr.y) * izy;
                float gw = __logf(__fdividef(tt.z - tt.x, pr.z)) * 5.0f;
                float gh = __logf(__fdividef(tt.w - tt.y, pr.w)) * 5.0f;
                dL -= smooth_l1(ld.x - gx) + smooth_l1(ld.y - gy)
                    + smooth_l1(ld.z - gw) + smooth_l1(ld.w - gh);
                dN -= 1;
            }
        }
        if (lane < MAXN) s_fp[lane] = valid ? fp : -1;
        #pragma unroll
        for (int o = 16; o; o >>= 1) {
            dL += __shfl_down_sync(0xFFFFFFFFu, dL, o);
            dC += __shfl_down_sync(0xFFFFFFFFu, dC, o);
            dN += __shfl_down_sync(0xFFFFFFFFu, dN, o);
        }
        if (lane == 0) { s_corrL = dL; s_corrC = dC; s_corrN = dN; }
    }
    __syncthreads();

    // ---- ownership zeroing of forced priors ----
    #pragma unroll
    for (int m = 0; m < MAXN; ++m) {
        int fp = s_fp[m];
        if (fp >= 0) {
            int f4 = fp >> 2;
            if (f4 < n4) {
                if ((f4 & 1023) == tid)
                    reinterpret_cast<float*>(&v4[f4 >> 10])[fp & 3] = 0.f;
            } else if (tid == (fp - (n4 << 2))) {
                vex = 0.f;
            }
        }
    }

    int np = s_np + s_corrN;
    int k  = min(3 * np, P - 1);

    // ---- pass 1: histogram of top 12 value bits ----
    {
        const float* vv = reinterpret_cast<const float*>(v4);
        #pragma unroll
        for (int i = 0; i < 24; ++i) {
            unsigned bin = __float_as_uint(vv[i]) >> 19;
            unsigned m = __match_any_sync(0xFFFFFFFFu, bin);
            if (lane == (__ffs(m) - 1)) atomicAdd(&s_hist[bin], __popc(m));
        }
        if (tid < tail) atomicAdd(&s_hist[__float_as_uint(vex) >> 19], 1);
    }
    __syncthreads();
    find_threshold(s_hist, k, tid, s_wt, s_out);
    unsigned Bs = (unsigned)s_out[0];
    int c1 = s_out[1];

    #pragma unroll
    for (int i = 0; i < 4; ++i) s_hist[tid + i * 1024] = 0;
    __syncthreads();

    // ---- pass 2: next 12 bits within bin Bs ----
    {
        const float* vv = reinterpret_cast<const float*>(v4);
        #pragma unroll
        for (int i = 0; i < 24; ++i) {
            unsigned bits = __float_as_uint(vv[i]);
            if ((bits >> 19) == Bs) atomicAdd(&s_hist[(bits >> 7) & 0xFFF], 1);
        }
        unsigned bx = __float_as_uint(vex);
        if (tid < tail && (bx >> 19) == Bs) atomicAdd(&s_hist[(bx >> 7) & 0xFFF], 1);
    }
    __syncthreads();
    find_threshold(s_hist, k - c1, tid, s_wt, s_out);
    unsigned Ss = (unsigned)s_out[0];

    unsigned Tcut = (Bs << 12) | Ss;
    float Tf = __uint_as_float((Bs << 19) | (Ss << 7));

    float sum = 0.f; int cnt = 0;
    {
        const float* vv = reinterpret_cast<const float*>(v4);
        #pragma unroll
        for (int i = 0; i < 24; ++i) {
            unsigned bits = __float_as_uint(vv[i]);
            if ((bits >> 7) > Tcut) { sum += vv[i]; cnt++; }
        }
        unsigned bx = __float_as_uint(vex);
        if (tid < tail && (bx >> 7) > Tcut) { sum += vex; cnt++; }
    }
    #pragma unroll
    for (int o = 16; o; o >>= 1) {
        sum += __shfl_down_sync(0xFFFFFFFFu, sum, o);
        cnt += __shfl_down_sync(0xFFFFFFFFu, cnt, o);
    }
    if (lane == 0) { s_fs[w] = sum; s_cs[w] = cnt; }
    __syncthreads();
    if (tid == 0) {
        float S = 0.f; int Cg = 0;
        #pragma unroll
        for (int i = 0; i < 32; ++i) { S += s_fs[i]; Cg += s_cs[i]; }
        g_bl[b] = s_L + s_corrL;
        g_bc[b] = s_Cp + s_corrC + S + (float)(k - Cg) * Tf;
        g_bn[b] = np;
        __threadfence();
        s_last = (atomicAdd(&g_ctr, 1) == (int)gridDim.x - 1) ? 1 : 0;
    }
    __syncthreads();

    if (s_last) {
        int B = gridDim.x;
        float l = 0.f, c = 0.f, nn = 0.f;
        if (tid < 64 && tid < B) {
            l = g_bl[tid]; c = g_bc[tid]; nn = (float)g_bn[tid];
        }
        if (tid < 64) {
            #pragma unroll
            for (int o = 16; o; o >>= 1) {
                l += __shfl_down_sync(0xFFFFFFFFu, l, o);
                c += __shfl_down_sync(0xFFFFFFFFu, c, o);
                nn += __shfl_down_sync(0xFFFFFFFFu, nn, o);
            }
            if (lane == 0) { s_fs[w] = l; s_fs[w + 8] = c; s_fs[w + 16] = nn; }
        }
        __syncthreads();
        if (tid == 0) {
            float Lr = s_fs[0] + s_fs[1];
            float Cr = s_fs[8] + s_fs[9];
            float Nr = s_fs[16] + s_fs[17];
            out[0] = Lr / Nr;
            out[1] = Cr / Nr;
            g_ctr = 0;
        }
    }
}

// ==========================================================================
extern "C" void kernel_launch(void* const* d_in, const int* in_sizes, int n_in,
                              void* d_out, int out_size)
{
    const float* loc    = (const float*)d_in[0];
    const float* conf   = (const float*)d_in[1];
    const float* priors = (const float*)d_in[2];
    const float* truths = (const float*)d_in[3];
    const int*   labels = (const int*)d_in[4];

    int P = in_sizes[2] / 4;
    int B = in_sizes[0] / (4 * P);
    int N = in_sizes[3] / (4 * B);

    int nA = (P + MROWS - 1) / MROWS;    // 24
    int nB = (P + LROWS - 1) / LROWS;    // 24

    dim3 fgrid(nA + nB, B);
    k_fused<<<fgrid, MTPB>>>(conf, priors, truths, P, N, nA);
    k_select<<<B, 1024>>>(loc, conf, priors, truths, labels, P, N, nA, (float*)d_out);
}

// round 7
// speedup vs baseline: 1.0411x; 1.0411x over previous
#include <cuda_runtime.h>
#include <cstdint>

#define MAXB   64
#define MAXN   16
#define NC     21
#define MTPB   256
#define MPPT   4
#define MROWS  (MTPB*MPPT)      // 1024
#define NABLK  24
#define MAXPP  24576
#define LTILE  128
#define LROWS  1024

// -------- scratch (__device__ globals; overwritten every launch) ----------
__device__ int                g_matchv[MAXB * MAXPP];   // bestn | pos<<31
__device__ float              g_mine  [MAXB * MAXPP];   // lse - row[0] (>= 0)
__device__ unsigned long long g_cK[MAXB * NABLK * MAXN];
__device__ float              g_bl[MAXB];
__device__ float              g_bc[MAXB];
__device__ int                g_bn[MAXB];
__device__ int                g_ctr = 0;                // reset by last block

__device__ __forceinline__ float smooth_l1(float d) {
    float ad = fabsf(d);
    return (ad < 1.0f) ? 0.5f * d * d : ad - 0.5f;
}

__device__ __forceinline__ void cp16(float* dst, const float4* src) {
    unsigned s = (unsigned)__cvta_generic_to_shared(dst);
    asm volatile("cp.async.cg.shared.global [%0], [%1], 16;\n" :: "r"(s), "l"(src));
}

// ==========================================================================
// Fused: blockIdx.x < nA -> IoU matching (ALU); else -> lse stream (DRAM).
__global__ __launch_bounds__(256, 5) void k_fused(
    const float* __restrict__ conf,
    const float* __restrict__ priors,
    const float* __restrict__ truths,
    int P, int N, int nA)
{
    __shared__ __align__(16) float s_conf[2 * LTILE * NC];   // 21.5 KB
    __shared__ float4 s_t[MAXN];
    __shared__ float  s_area[MAXN];
    __shared__ unsigned long long s_best[MAXN];

    int b   = blockIdx.y;
    int tid = threadIdx.x;

    if (blockIdx.x < nA) {
        // ================= MATCH PATH =================
        int p0   = blockIdx.x * MROWS;
        int lane = tid & 31;

        if (tid < MAXN) {
            s_best[tid] = 0ULL;
            if (tid < N) {
                float4 t = reinterpret_cast<const float4*>(truths)[b * N + tid];
                s_t[tid] = t;
                s_area[tid] = (t.z - t.x) * (t.w - t.y);
            }
        }
        __syncthreads();

        float px1[MPPT], py1[MPPT], px2[MPPT], py2[MPPT], ab[MPPT];
        #pragma unroll
        for (int i = 0; i < MPPT; ++i) {
            int p  = p0 + i * MTPB + tid;
            int pc = min(p, P - 1);                 // clamp; dups lose ties via ~p
            float4 pr = reinterpret_cast<const float4*>(priors)[pc];
            float hx = pr.z * 0.5f, hy = pr.w * 0.5f;
            px1[i] = pr.x - hx; py1[i] = pr.y - hy;
            px2[i] = pr.x + hx; py2[i] = pr.y + hy;
            ab[i]  = pr.z * pr.w;
        }

        float bt[MPPT];
        int   bn[MPPT];
        #pragma unroll
        for (int i = 0; i < MPPT; ++i) { bt[i] = -1.f; bn[i] = 0; }

        #pragma unroll
        for (int n = 0; n < MAXN; ++n) {
            if (n < N) {
                float4 t = s_t[n];
                float sa = s_area[n];
                float biou = -1.f;
                int   bp   = 0x7FFFFFFF;
                #pragma unroll
                for (int i = 0; i < MPPT; ++i) {
                    float w = fmaxf(fminf(t.z, px2[i]) - fmaxf(t.x, px1[i]), 0.f);
                    float h = fmaxf(fminf(t.w, py2[i]) - fmaxf(t.y, py1[i]), 0.f);
                    float inter = w * h;
                    float uni   = sa + ab[i] - inter;
                    float iou   = __fdividef(inter, uni);
                    if (iou > bt[i]) { bt[i] = iou; bn[i] = n; }               // tie -> lowest n
                    if (iou > biou)  { biou = iou; bp = p0 + i * MTPB + tid; } // tie -> lowest p
                }
                unsigned long long key =
                    ((unsigned long long)__float_as_uint(fmaxf(biou, 0.f)) << 32)
                    | (unsigned)~bp;
                #pragma unroll
                for (int o = 16; o; o >>= 1) {
                    unsigned long long ok = __shfl_down_sync(0xFFFFFFFFu, key, o);
                    key = (ok > key) ? ok : key;
                }
                if (lane == 0) atomicMax(&s_best[n], key);
            }
        }

        #pragma unroll
        for (int i = 0; i < MPPT; ++i) {
            int p = p0 + i * MTPB + tid;
            if (p < P) {
                int pos = (bt[i] >= 0.5f) ? 1 : 0;
                g_matchv[(size_t)b * P + p] = bn[i] | (pos << 31);
            }
        }
        __syncthreads();
        if (tid < MAXN)
            g_cK[((size_t)b * NABLK + blockIdx.x) * MAXN + tid] = s_best[tid];

    } else {
        // ================= LSE PATH =================
        int bx   = blockIdx.x - nA;
        int r0   = bx * LROWS;
        int rows = min(LROWS, P - r0);
        int nt   = (rows + LTILE - 1) / LTILE;

        auto stage = [&](int t) {
            int tr = min(LTILE, rows - t * LTILE);
            int total = tr * NC;
            int n4 = total >> 2;
            const float* srcf = conf + ((size_t)b * P + r0 + t * LTILE) * NC;
            const float4* src4 = reinterpret_cast<const float4*>(srcf);
            float* dst = s_conf + (t & 1) * (LTILE * NC);
            for (int i = tid; i < n4; i += MTPB) cp16(dst + i * 4, src4 + i);
            for (int i = (n4 << 2) + tid; i < total; i += MTPB) dst[i] = srcf[i];
            asm volatile("cp.async.commit_group;\n");
        };

        stage(0);
        for (int t = 0; t < nt; ++t) {
            if (t + 1 < nt) {
                stage(t + 1);
                asm volatile("cp.async.wait_group 1;\n");
            } else {
                asm volatile("cp.async.wait_group 0;\n");
            }
            __syncthreads();

            int r = t * LTILE + tid;
            if (tid < LTILE && r < rows) {
                const float* row = s_conf + (t & 1) * (LTILE * NC) + tid * NC;
                float e0 = 0.f, e1 = 0.f, e2 = 0.f, e3 = 0.f;
                #pragma unroll
                for (int c = 0; c < NC; c += 4) {
                    e0 += __expf(row[c]);
                    if (c + 1 < NC) e1 += __expf(row[c + 1]);
                    if (c + 2 < NC) e2 += __expf(row[c + 2]);
                    if (c + 3 < NC) e3 += __expf(row[c + 3]);
                }
                float lse = __logf((e0 + e1) + (e2 + e3));
                g_mine[(size_t)b * P + r0 + r] = lse - row[0];   // >= 0
            }
            __syncthreads();
        }
    }
}

// ==========================================================================
// suffix-scan over 4096-bin histogram; 1024 threads, 4 bins each.
__device__ __forceinline__ void find_threshold(
    int* s_hist, int k, int tid, int* s_wt, int* s_out)
{
    int w = tid >> 5, lane = tid & 31;
    int base = tid * 4;
    int l[4]; int loc = 0;
    #pragma unroll
    for (int j = 0; j < 4; ++j) { l[j] = s_hist[base + j]; loc += l[j]; }
    int incl = loc;
    #pragma unroll
    for (int o = 1; o < 32; o <<= 1) {
        int x = __shfl_up_sync(0xFFFFFFFFu, incl, o);
        if (lane >= o) incl += x;
    }
    int wsum = __shfl_sync(0xFFFFFFFFu, incl, 31);
    if (lane == 31) s_wt[w] = wsum;
    __syncthreads();
    int wa = 0;
    #pragma unroll
    for (int w2 = 0; w2 < 32; ++w2) if (w2 > w) wa += s_wt[w2];
    int above = wa + (wsum - incl);          // count in bins >= base+4
    if (above < k && above + loc >= k) {
        int run = 0;
        #pragma unroll
        for (int j = 3; j >= 0; --j) {
            run += l[j];
            if (above + run >= k) { s_out[0] = base + j; s_out[1] = above + run - l[j]; break; }
        }
    }
    __syncthreads();
}

// ==========================================================================
// k_select: warp 0 first resolves forced priors, adds their contribution,
// and ZEROES g_mine/g_matchv for them in gmem (so the scan never sees them).
// Then all threads scan mine+match (fully static register arrays), handle
// positives inline, and run the two-level histogram top-k.
__global__ __launch_bounds__(1024) void k_select(
    const float* __restrict__ loc,
    const float* __restrict__ conf,
    const float* __restrict__ priors,
    const float* __restrict__ truths,
    const int*   __restrict__ labels,
    int P, int N, int nA, float* __restrict__ out)
{
    int b = blockIdx.x, tid = threadIdx.x;
    int w = tid >> 5, lane = tid & 31;

    __shared__ int    s_hist[4096];
    __shared__ int    s_wt[32];
    __shared__ int    s_out[2];
    __shared__ float  s_fs[32], s_fc[32];
    __shared__ int    s_cs[32];
    __shared__ float4 s_t[MAXN];
    __shared__ int    s_lab[MAXN];
    __shared__ float  s_corrL, s_corrC;
    __shared__ int    s_corrN, s_last;

    if (tid < N) {
        s_t[tid]   = reinterpret_cast<const float4*>(truths)[b * N + tid];
        s_lab[tid] = labels[b * N + tid];
    }
    #pragma unroll
    for (int i = 0; i < 4; ++i) s_hist[tid + i * 1024] = 0;
    __syncthreads();

    // ---- warp 0: forced priors -> corrections + gmem zeroing ----
    if (w == 0) {
        unsigned long long best = 0ULL;
        if (lane < N)
            for (int j = 0; j < nA; ++j) {
                unsigned long long k2 = g_cK[((size_t)b * NABLK + j) * MAXN + lane];
                best = (k2 > best) ? k2 : best;
            }
        int fp = (lane < N) ? (int)~(unsigned)best : -1;
        bool valid = (lane < N);
        #pragma unroll
        for (int m = 0; m < MAXN; ++m) {
            int pm = __shfl_sync(0xFFFFFFFFu, fp, m);
            if (m < N && m > lane && pm == fp) valid = false;   // last truth wins
        }
        float dL = 0.f, dC = 0.f; int dN = 0;
        if (valid) {
            int p = fp;
            const float* crow = conf + ((size_t)b * P + p) * NC;
            float lse = g_mine[(size_t)b * P + p] + crow[0];
            float4 pr = reinterpret_cast<const float4*>(priors)[p];
            float4 ld = reinterpret_cast<const float4*>(loc)[(size_t)b * P + p];
            float4 tt = s_t[lane];
            dC += lse - crow[s_lab[lane] + 1];
            float gx = __fdividef((tt.x + tt.z) * 0.5f - pr.x, 0.1f * pr.z);
            float gy = __fdividef((tt.y + tt.w) * 0.5f - pr.y, 0.1f * pr.w);
            float gw = __logf(__fdividef(tt.z - tt.x, pr.z)) * 5.0f;
            float gh = __logf(__fdividef(tt.w - tt.y, pr.w)) * 5.0f;
            dL += smooth_l1(ld.x - gx) + smooth_l1(ld.y - gy)
                + smooth_l1(ld.z - gw) + smooth_l1(ld.w - gh);
            dN += 1;
            g_mine  [(size_t)b * P + p] = 0.f;   // exclude from mining
            g_matchv[(size_t)b * P + p] = 0;     // scan won't double-count
        }
        #pragma unroll
        for (int o = 16; o; o >>= 1) {
            dL += __shfl_down_sync(0xFFFFFFFFu, dL, o);
            dC += __shfl_down_sync(0xFFFFFFFFu, dC, o);
            dN += __shfl_down_sync(0xFFFFFFFFu, dN, o);
        }
        if (lane == 0) { s_corrL = dL; s_corrC = dC; s_corrN = dN; }
    }
    __syncthreads();   // orders warp0's gmem writes before the block-wide loads

    // ---- scan: load mine + match, handle (non-forced) positives inline ----
    const int V4 = 6;            // 6 * 1024 * 4 = 24576 >= P
    float4 v4[V4];
    float L = 0.f, C = 0.f; int n = 0;
    const float4* mv  = reinterpret_cast<const float4*>(g_mine   + (size_t)b * P);
    const int4*   mm4 = reinterpret_cast<const int4*>  (g_matchv + (size_t)b * P);
    int n4 = P >> 2;

    auto do_pos = [&](int mm, float& vref, int p) {
        if (mm < 0) {
            int bnn = mm & 0x7FFFFFFF;
            const float* crow = conf + ((size_t)b * P + p) * NC;
            float lse = vref + crow[0];
            C += lse - crow[s_lab[bnn] + 1];
            n++;
            float4 tt = s_t[bnn];
            float4 pr = reinterpret_cast<const float4*>(priors)[p];
            float gx = __fdividef((tt.x + tt.z) * 0.5f - pr.x, 0.1f * pr.z);
            float gy = __fdividef((tt.y + tt.w) * 0.5f - pr.y, 0.1f * pr.w);
            float gw = __logf(__fdividef(tt.z - tt.x, pr.z)) * 5.0f;
            float gh = __logf(__fdividef(tt.w - tt.y, pr.w)) * 5.0f;
            float4 ld = reinterpret_cast<const float4*>(loc)[(size_t)b * P + p];
            L += smooth_l1(ld.x - gx) + smooth_l1(ld.y - gy)
               + smooth_l1(ld.z - gw) + smooth_l1(ld.w - gh);
            vref = 0.f;
        }
    };

    #pragma unroll
    for (int i = 0; i < V4; ++i) {
        int j = tid + i * 1024;
        float4 v = make_float4(0.f, 0.f, 0.f, 0.f);
        if (j < n4) {
            v = mv[j];
            int4 m = mm4[j];
            int p = 4 * j;
            do_pos(m.x, v.x, p);
            do_pos(m.y, v.y, p + 1);
            do_pos(m.z, v.z, p + 2);
            do_pos(m.w, v.w, p + 3);
        }
        v4[i] = v;
    }
    int tail = P & 3;
    float vex = 0.f;
    if (tid < tail) {
        int p = (P & ~3) + tid;
        vex = g_mine[(size_t)b * P + p];
        do_pos(g_matchv[(size_t)b * P + p], vex, p);
    }

    // reduce scan partials
    #pragma unroll
    for (int o = 16; o; o >>= 1) {
        L += __shfl_down_sync(0xFFFFFFFFu, L, o);
        C += __shfl_down_sync(0xFFFFFFFFu, C, o);
        n += __shfl_down_sync(0xFFFFFFFFu, n, o);
    }
    if (lane == 0) { s_fs[w] = L; s_fc[w] = C; s_cs[w] = n; }
    __syncthreads();

    float Lt = 0.f, Ct = 0.f; int np = 0;
    #pragma unroll
    for (int i = 0; i < 32; ++i) { Lt += s_fs[i]; Ct += s_fc[i]; np += s_cs[i]; }
    Lt += s_corrL; Ct += s_corrC; np += s_corrN;
    int k = min(3 * np, P - 1);

    // ---- pass 1: histogram of top 12 value bits ----
    {
        const float* vv = reinterpret_cast<const float*>(v4);
        #pragma unroll
        for (int i = 0; i < 24; ++i) {
            unsigned bin = __float_as_uint(vv[i]) >> 19;
            unsigned m = __match_any_sync(0xFFFFFFFFu, bin);
            if (lane == (__ffs(m) - 1)) atomicAdd(&s_hist[bin], __popc(m));
        }
        if (tid < tail) atomicAdd(&s_hist[__float_as_uint(vex) >> 19], 1);
    }
    __syncthreads();
    find_threshold(s_hist, k, tid, s_wt, s_out);
    unsigned Bs = (unsigned)s_out[0];
    int c1 = s_out[1];

    #pragma unroll
    for (int i = 0; i < 4; ++i) s_hist[tid + i * 1024] = 0;
    __syncthreads();

    // ---- pass 2: next 12 bits within bin Bs ----
    {
        const float* vv = reinterpret_cast<const float*>(v4);
        #pragma unroll
        for (int i = 0; i < 24; ++i) {
            unsigned bits = __float_as_uint(vv[i]);
            if ((bits >> 19) == Bs) atomicAdd(&s_hist[(bits >> 7) & 0xFFF], 1);
        }
        unsigned bx = __float_as_uint(vex);
        if (tid < tail && (bx >> 19) == Bs) atomicAdd(&s_hist[(bx >> 7) & 0xFFF], 1);
    }
    __syncthreads();
    find_threshold(s_hist, k - c1, tid, s_wt, s_out);
    unsigned Ss = (unsigned)s_out[0];

    unsigned Tcut = (Bs << 12) | Ss;
    float Tf = __uint_as_float((Bs << 19) | (Ss << 7));

    float sum = 0.f; int cnt = 0;
    {
        const float* vv = reinterpret_cast<const float*>(v4);
        #pragma unroll
        for (int i = 0; i < 24; ++i) {
            unsigned bits = __float_as_uint(vv[i]);
            if ((bits >> 7) > Tcut) { sum += vv[i]; cnt++; }
        }
        unsigned bx = __float_as_uint(vex);
        if (tid < tail && (bx >> 7) > Tcut) { sum += vex; cnt++; }
    }
    #pragma unroll
    for (int o = 16; o; o >>= 1) {
        sum += __shfl_down_sync(0xFFFFFFFFu, sum, o);
        cnt += __shfl_down_sync(0xFFFFFFFFu, cnt, o);
    }
    if (lane == 0) { s_fs[w] = sum; s_cs[w] = cnt; }
    __syncthreads();
    if (tid == 0) {
        float S = 0.f; int Cg = 0;
        #pragma unroll
        for (int i = 0; i < 32; ++i) { S += s_fs[i]; Cg += s_cs[i]; }
        g_bl[b] = Lt;
        g_bc[b] = Ct + S + (float)(k - Cg) * Tf;
        g_bn[b] = np;
        __threadfence();
        s_last = (atomicAdd(&g_ctr, 1) == (int)gridDim.x - 1) ? 1 : 0;
    }
    __syncthreads();

    if (s_last) {
        int B = gridDim.x;
        float l = 0.f, c = 0.f, nn = 0.f;
        if (tid < 64 && tid < B) {
            l = g_bl[tid]; c = g_bc[tid]; nn = (float)g_bn[tid];
        }
        if (tid < 64) {
            #pragma unroll
            for (int o = 16; o; o >>= 1) {
                l += __shfl_down_sync(0xFFFFFFFFu, l, o);
                c += __shfl_down_sync(0xFFFFFFFFu, c, o);
                nn += __shfl_down_sync(0xFFFFFFFFu, nn, o);
            }
            if (lane == 0) { s_fs[w] = l; s_fc[w] = c; s_fs[w + 16] = nn; }
        }
        __syncthreads();
        if (tid == 0) {
            float Lr = s_fs[0] + s_fs[1];
            float Cr = s_fc[0] + s_fc[1];
            float Nr = s_fs[16] + s_fs[17];
            out[0] = Lr / Nr;
            out[1] = Cr / Nr;
            g_ctr = 0;
        }
    }
}

// ==========================================================================
extern "C" void kernel_launch(void* const* d_in, const int* in_sizes, int n_in,
                              void* d_out, int out_size)
{
    const float* loc    = (const float*)d_in[0];
    const float* conf   = (const float*)d_in[1];
    const float* priors = (const float*)d_in[2];
    const float* truths = (const float*)d_in[3];
    const int*   labels = (const int*)d_in[4];

    int P = in_sizes[2] / 4;
    int B = in_sizes[0] / (4 * P);
    int N = in_sizes[3] / (4 * B);

    int nA = (P + MROWS - 1) / MROWS;    // 24
    int nB = (P + LROWS - 1) / LROWS;    // 24

    dim3 fgrid(nA + nB, B);
    k_fused<<<fgrid, MTPB>>>(conf, priors, truths, P, N, nA);
    k_select<<<B, 1024>>>(loc, conf, priors, truths, labels, P, N, nA, (float*)d_out);
}